// round 1
// baseline (speedup 1.0000x reference)
#include <cuda_runtime.h>

#define HIDDEN 8
#define RES 64
#define NBATCH 2048
#define TILE_H 32
#define SROWS 36           // TILE_H + 4 halo rows
#define SROW 72            // padded smem row stride (floats): cols 0..67 used
#define SP_FLOATS (HIDDEN * SROWS * SROW)
#define SMEM_FLOATS (SP_FLOATS + 200 + 64 + 64 + 8 + 8 + 8)
#define SMEM_BYTES (SMEM_FLOATS * 4)

// D4-symmetrized, per-kernel-zero-mean 5x5 depthwise weights
__device__ float g_w[HIDDEN * 25];

__global__ void prep_weights_kernel(const float* __restrict__ filter1) {
    __shared__ float sw[HIDDEN * 25];
    int t = threadIdx.x;
    float wv = 0.f;
    int h = 0;
    if (t < 200) {
        h = t / 25;
        int idx = t % 25;
        int i = idx / 5, j = idx % 5;
        const float* f = filter1 + h * 25;
        float s = f[i*5 + j] + f[(4-i)*5 + j] + f[i*5 + (4-j)] + f[(4-i)*5 + (4-j)]
                + f[j*5 + i] + f[(4-j)*5 + i] + f[j*5 + (4-i)] + f[(4-j)*5 + (4-i)];
        wv = 0.125f * s;
        sw[t] = wv;
    }
    __syncthreads();
    if (t < 200) {
        float m = 0.f;
        #pragma unroll
        for (int k = 0; k < 25; k++) m += sw[h * 25 + k];
        g_w[t] = wv - m * (1.0f / 25.0f);
    }
}

__device__ __forceinline__ float lrelu(float x) {
    return fmaxf(x, 0.f) + 0.01f * fminf(x, 0.f);
}

__device__ __forceinline__ float tanh_fast(float x) {
    float y;
    asm("tanh.approx.f32 %0, %1;" : "=f"(y) : "f"(x));
    return y;
}

__global__ __launch_bounds__(256, 2)
void ca_fused_kernel(const float* __restrict__ psi,
                     const float* __restrict__ bias1,
                     const float* __restrict__ w2,
                     const float* __restrict__ b2,
                     const float* __restrict__ w3,
                     const float* __restrict__ b3,
                     float* __restrict__ out)
{
    extern __shared__ __align__(16) float sm[];
    float* sp  = sm;                 // [8][SROWS][SROW], pixel x stored at col x+2
    float* swt = sm + SP_FLOATS;     // 200 conv weights
    float* sw2 = swt + 200;          // 64
    float* sw3 = sw2 + 64;           // 64
    float* sb1 = sw3 + 64;           // 8
    float* sb2 = sb1 + 8;            // 8
    float* sb3 = sb2 + 8;            // 8

    const int tid = threadIdx.x;
    const int b   = blockIdx.y;
    const int y0  = blockIdx.x * TILE_H;

    // Stage small params into smem
    if (tid < 200) swt[tid] = g_w[tid];
    if (tid < 64)               sw2[tid]       = w2[tid];
    else if (tid < 128)         sw3[tid - 64]  = w3[tid - 64];
    else if (tid < 136)         sb1[tid - 128] = bias1[tid - 128];
    else if (tid < 144)         sb2[tid - 136] = b2[tid - 136];
    else if (tid < 152)         sb3[tid - 144] = b3[tid - 144];

    // Zero the x-halo columns (cols 0,1,66,67) for all channels/rows
    for (int k = tid; k < HIDDEN * SROWS * 4; k += 256) {
        int c  = k & 3;
        int rr = k >> 2;                    // ch*SROWS + r
        int col = (c < 2) ? c : (64 + c);   // 0,1,66,67
        sp[rr * SROW + col] = 0.f;
    }

    // Interior fill: float4 global loads, zero rows outside the image (y pad)
    const float* pb = psi + (size_t)b * (HIDDEN * RES * RES);
    for (int k = tid; k < HIDDEN * SROWS * 16; k += 256) {
        int q  = k & 15;                     // float4 index within row
        int rr = k >> 4;                     // ch*SROWS + r
        int r  = rr % SROWS;
        int ch = rr / SROWS;
        int gy = y0 + r - 2;
        float4 v = make_float4(0.f, 0.f, 0.f, 0.f);
        if ((unsigned)gy < RES)
            v = *(const float4*)(pb + (ch * RES + gy) * RES + q * 4);
        float2* d = (float2*)(sp + rr * SROW + q * 4 + 2);   // col = x+2 (8B aligned)
        d[0] = make_float2(v.x, v.y);
        d[1] = make_float2(v.z, v.w);
    }
    __syncthreads();

    // Each thread: 4 x-pixels (x0..x0+3) x 2 y-rows (ry, ry+1), all 8 channels
    const int tx = tid & 15;
    const int ty = tid >> 4;
    const int x0 = tx << 2;      // output x base (0..60)
    const int ry = ty << 1;      // output row base within tile (0..30)

    float z[8][8];               // z[channel][py*4 + px] after conv+bias+lrelu

    #pragma unroll
    for (int ch = 0; ch < 8; ch++) {
        float w[25];
        #pragma unroll
        for (int k = 0; k < 25; k++) w[k] = swt[ch * 25 + k];

        float bv = sb1[ch];
        float acc[8];
        #pragma unroll
        for (int p = 0; p < 8; p++) acc[p] = bv;

        // smem window: out row ry uses smem rows ry..ry+4; row ry+1 uses ry+1..ry+5
        const float* base = sp + (ch * SROWS + ry) * SROW + x0;  // col x0 == x0-2 pixel
        #pragma unroll
        for (int r = 0; r < 6; r++) {
            float4 A = *(const float4*)(base + r * SROW);
            float4 B = *(const float4*)(base + r * SROW + 4);
            float wv[8] = {A.x, A.y, A.z, A.w, B.x, B.y, B.z, B.w};
            if (r <= 4) {   // contributes to out row ry with weight-row r
                #pragma unroll
                for (int dx = 0; dx < 5; dx++) {
                    float ww = w[r * 5 + dx];
                    acc[0] = fmaf(ww, wv[dx + 0], acc[0]);
                    acc[1] = fmaf(ww, wv[dx + 1], acc[1]);
                    acc[2] = fmaf(ww, wv[dx + 2], acc[2]);
                    acc[3] = fmaf(ww, wv[dx + 3], acc[3]);
                }
            }
            if (r >= 1) {   // contributes to out row ry+1 with weight-row r-1
                #pragma unroll
                for (int dx = 0; dx < 5; dx++) {
                    float ww = w[(r - 1) * 5 + dx];
                    acc[4] = fmaf(ww, wv[dx + 0], acc[4]);
                    acc[5] = fmaf(ww, wv[dx + 1], acc[5]);
                    acc[6] = fmaf(ww, wv[dx + 2], acc[6]);
                    acc[7] = fmaf(ww, wv[dx + 3], acc[7]);
                }
            }
        }
        #pragma unroll
        for (int p = 0; p < 8; p++) z[ch][p] = lrelu(acc[p]);
    }

    // Per-pixel 8x8 GEMMs + residual tanh, processed per y-row (4 px at a time)
    float* ob = out + (size_t)b * (HIDDEN * RES * RES);
    #pragma unroll
    for (int py = 0; py < 2; py++) {
        float z2[8][4];
        #pragma unroll
        for (int o = 0; o < 8; o++) {
            float c0 = sb2[o], c1 = c0, c2 = c0, c3 = c0;
            #pragma unroll
            for (int i = 0; i < 8; i++) {
                float ww = sw2[o * 8 + i];
                c0 = fmaf(ww, z[i][py * 4 + 0], c0);
                c1 = fmaf(ww, z[i][py * 4 + 1], c1);
                c2 = fmaf(ww, z[i][py * 4 + 2], c2);
                c3 = fmaf(ww, z[i][py * 4 + 3], c3);
            }
            z2[o][0] = lrelu(c0);
            z2[o][1] = lrelu(c1);
            z2[o][2] = lrelu(c2);
            z2[o][3] = lrelu(c3);
        }
        const int gy = y0 + ry + py;
        #pragma unroll
        for (int o = 0; o < 8; o++) {
            float h0 = sb3[o], h1 = h0, h2 = h0, h3 = h0;
            #pragma unroll
            for (int i = 0; i < 8; i++) {
                float ww = sw3[o * 8 + i];
                h0 = fmaf(ww, z2[i][0], h0);
                h1 = fmaf(ww, z2[i][1], h1);
                h2 = fmaf(ww, z2[i][2], h2);
                h3 = fmaf(ww, z2[i][3], h3);
            }
            // residual psi at the output pixel, from smem (col = x+2, row = +2)
            const float* pc = sp + (o * SROWS + ry + py + 2) * SROW + x0 + 2;
            float4 res;
            res.x = tanh_fast(pc[0] + h0);
            res.y = tanh_fast(pc[1] + h1);
            res.z = tanh_fast(pc[2] + h2);
            res.w = tanh_fast(pc[3] + h3);
            *(float4*)(ob + (o * RES + gy) * RES + x0) = res;
        }
    }
}

extern "C" void kernel_launch(void* const* d_in, const int* in_sizes, int n_in,
                              void* d_out, int out_size) {
    const float* psi     = (const float*)d_in[0];
    const float* filter1 = (const float*)d_in[1];
    const float* bias1   = (const float*)d_in[2];
    const float* w2      = (const float*)d_in[3];
    const float* b2      = (const float*)d_in[4];
    const float* w3      = (const float*)d_in[5];
    const float* b3      = (const float*)d_in[6];
    float* out = (float*)d_out;

    cudaFuncSetAttribute(ca_fused_kernel,
                         cudaFuncAttributeMaxDynamicSharedMemorySize, SMEM_BYTES);

    prep_weights_kernel<<<1, 256>>>(filter1);

    dim3 grid(RES / TILE_H, NBATCH);
    ca_fused_kernel<<<grid, 256, SMEM_BYTES>>>(psi, bias1, w2, b2, w3, b3, out);
}

// round 3
// speedup vs baseline: 1.4279x; 1.4279x over previous
#include <cuda_runtime.h>

#define HIDDEN 8
#define RES 64
#define NBATCH 2048
#define TILE_H 16
#define SROWS 20           // TILE_H + 4 halo rows
#define SROW 72            // padded smem row stride (floats): cols 0..67 used
#define SP_FLOATS (HIDDEN * SROWS * SROW)
#define SMEM_FLOATS (SP_FLOATS + 200 + 64 + 64 + 8 + 8 + 8)
#define SMEM_BYTES (SMEM_FLOATS * 4)

// D4-symmetrized, per-kernel-zero-mean 5x5 depthwise weights
__device__ float g_w[HIDDEN * 25];

__global__ void prep_weights_kernel(const float* __restrict__ filter1) {
    __shared__ float sw[HIDDEN * 25];
    int t = threadIdx.x;
    float wv = 0.f;
    int h = 0;
    if (t < 200) {
        h = t / 25;
        int idx = t % 25;
        int i = idx / 5, j = idx % 5;
        const float* f = filter1 + h * 25;
        float s = f[i*5 + j] + f[(4-i)*5 + j] + f[i*5 + (4-j)] + f[(4-i)*5 + (4-j)]
                + f[j*5 + i] + f[(4-j)*5 + i] + f[j*5 + (4-i)] + f[(4-j)*5 + (4-i)];
        wv = 0.125f * s;
        sw[t] = wv;
    }
    __syncthreads();
    if (t < 200) {
        float m = 0.f;
        #pragma unroll
        for (int k = 0; k < 25; k++) m += sw[h * 25 + k];
        g_w[t] = wv - m * (1.0f / 25.0f);
    }
}

__device__ __forceinline__ float lrelu(float x) {
    return fmaxf(x, 0.f) + 0.01f * fminf(x, 0.f);
}

__device__ __forceinline__ float tanh_fast(float x) {
    float y;
    asm("tanh.approx.f32 %0, %1;" : "=f"(y) : "f"(x));
    return y;
}

__global__ __launch_bounds__(256, 3)
void ca_fused_kernel(const float* __restrict__ psi,
                     const float* __restrict__ bias1,
                     const float* __restrict__ w2,
                     const float* __restrict__ b2,
                     const float* __restrict__ w3,
                     const float* __restrict__ b3,
                     float* __restrict__ out)
{
    extern __shared__ __align__(16) float sm[];
    float* sp  = sm;                 // [8][SROWS][SROW], pixel x stored at col x+2
    float* swt = sm + SP_FLOATS;     // 200 conv weights
    float* sw2 = swt + 200;          // 64 (transposed: sw2[i*8+o] = w2[o][i])
    float* sw3 = sw2 + 64;           // 64
    float* sb1 = sw3 + 64;           // 8
    float* sb2 = sb1 + 8;            // 8
    float* sb3 = sb2 + 8;            // 8

    const int tid = threadIdx.x;
    const int b   = blockIdx.y;
    const int y0  = blockIdx.x * TILE_H;

    // Stage small params into smem (w2 transposed so inner-loop reads are i-major)
    if (tid < 200) swt[tid] = g_w[tid];
    if (tid < 64) {
        int o = tid >> 3, i = tid & 7;
        sw2[i * 8 + o] = w2[tid];
    } else if (tid < 128)       sw3[tid - 64]  = w3[tid - 64];
    else if (tid < 136)         sb1[tid - 128] = bias1[tid - 128];
    else if (tid < 144)         sb2[tid - 136] = b2[tid - 136];
    else if (tid < 152)         sb3[tid - 144] = b3[tid - 144];

    // Zero the x-halo columns (cols 0,1,66,67) for all channels/rows
    for (int k = tid; k < HIDDEN * SROWS * 4; k += 256) {
        int c  = k & 3;
        int rr = k >> 2;                    // ch*SROWS + r
        int col = (c < 2) ? c : (64 + c);   // 0,1,66,67
        sp[rr * SROW + col] = 0.f;
    }

    // Interior fill: float4 global loads, zero rows outside the image (y pad)
    const float* pb = psi + (size_t)b * (HIDDEN * RES * RES);
    for (int k = tid; k < HIDDEN * SROWS * 16; k += 256) {
        int q  = k & 15;                     // float4 index within row
        int rr = k >> 4;                     // ch*SROWS + r
        int r  = rr % SROWS;
        int ch = rr / SROWS;
        int gy = y0 + r - 2;
        float4 v = make_float4(0.f, 0.f, 0.f, 0.f);
        if ((unsigned)gy < RES)
            v = *(const float4*)(pb + (ch * RES + gy) * RES + q * 4);
        float2* d = (float2*)(sp + rr * SROW + q * 4 + 2);   // col = x+2 (8B aligned)
        d[0] = make_float2(v.x, v.y);
        d[1] = make_float2(v.z, v.w);
    }
    __syncthreads();

    // Each thread: 4 x-pixels (x0..x0+3) of ONE output row (ry), all 8 channels.
    const int tx = tid & 15;
    const int ry = tid >> 4;     // output row within tile (0..15)
    const int x0 = tx << 2;      // output x base (0..60)

    // z2[o][p]: accumulators of the first 8x8 GEMM, fused into the conv channel
    // loop so the conv activations z never need to be stored.
    float z2[8][4];
    #pragma unroll
    for (int o = 0; o < 8; o++) {
        float bv = sb2[o];
        z2[o][0] = bv; z2[o][1] = bv; z2[o][2] = bv; z2[o][3] = bv;
    }

    #pragma unroll
    for (int ch = 0; ch < 8; ch++) {
        float w[25];
        #pragma unroll
        for (int k = 0; k < 25; k++) w[k] = swt[ch * 25 + k];

        float bv = sb1[ch];
        float a0 = bv, a1 = bv, a2 = bv, a3 = bv;

        // smem window: out row ry uses smem rows ry..ry+4 (stored with +0 offset
        // because smem row r holds image row y0+r-2)
        const float* base = sp + (ch * SROWS + ry) * SROW + x0;  // col x0 == pixel x0-2
        #pragma unroll
        for (int r = 0; r < 5; r++) {
            float4 A = *(const float4*)(base + r * SROW);
            float4 B = *(const float4*)(base + r * SROW + 4);
            float wv[8] = {A.x, A.y, A.z, A.w, B.x, B.y, B.z, B.w};
            #pragma unroll
            for (int dx = 0; dx < 5; dx++) {
                float ww = w[r * 5 + dx];
                a0 = fmaf(ww, wv[dx + 0], a0);
                a1 = fmaf(ww, wv[dx + 1], a1);
                a2 = fmaf(ww, wv[dx + 2], a2);
                a3 = fmaf(ww, wv[dx + 3], a3);
            }
        }
        float v0 = lrelu(a0), v1 = lrelu(a1), v2 = lrelu(a2), v3 = lrelu(a3);

        // Fused GEMM-1 accumulation: z2[o] += w2[o][ch] * v
        #pragma unroll
        for (int o = 0; o < 8; o++) {
            float ww = sw2[ch * 8 + o];
            z2[o][0] = fmaf(ww, v0, z2[o][0]);
            z2[o][1] = fmaf(ww, v1, z2[o][1]);
            z2[o][2] = fmaf(ww, v2, z2[o][2]);
            z2[o][3] = fmaf(ww, v3, z2[o][3]);
        }
    }

    // leaky_relu on z2
    #pragma unroll
    for (int o = 0; o < 8; o++) {
        z2[o][0] = lrelu(z2[o][0]);
        z2[o][1] = lrelu(z2[o][1]);
        z2[o][2] = lrelu(z2[o][2]);
        z2[o][3] = lrelu(z2[o][3]);
    }

    // GEMM-2 + residual + tanh + store
    float* ob = out + (size_t)b * (HIDDEN * RES * RES);
    const int gy = y0 + ry;
    #pragma unroll
    for (int o = 0; o < 8; o++) {
        float h0 = sb3[o], h1 = h0, h2 = h0, h3 = h0;
        #pragma unroll
        for (int i = 0; i < 8; i++) {
            float ww = sw3[o * 8 + i];
            h0 = fmaf(ww, z2[i][0], h0);
            h1 = fmaf(ww, z2[i][1], h1);
            h2 = fmaf(ww, z2[i][2], h2);
            h3 = fmaf(ww, z2[i][3], h3);
        }
        // residual psi at the output pixel, from smem (col = x+2, row = ry+2)
        const float* pc = sp + (o * SROWS + ry + 2) * SROW + x0 + 2;
        float4 res;
        res.x = tanh_fast(pc[0] + h0);
        res.y = tanh_fast(pc[1] + h1);
        res.z = tanh_fast(pc[2] + h2);
        res.w = tanh_fast(pc[3] + h3);
        *(float4*)(ob + (o * RES + gy) * RES + x0) = res;
    }
}

extern "C" void kernel_launch(void* const* d_in, const int* in_sizes, int n_in,
                              void* d_out, int out_size) {
    const float* psi     = (const float*)d_in[0];
    const float* filter1 = (const float*)d_in[1];
    const float* bias1   = (const float*)d_in[2];
    const float* w2      = (const float*)d_in[3];
    const float* b2      = (const float*)d_in[4];
    const float* w3      = (const float*)d_in[5];
    const float* b3      = (const float*)d_in[6];
    float* out = (float*)d_out;

    cudaFuncSetAttribute(ca_fused_kernel,
                         cudaFuncAttributeMaxDynamicSharedMemorySize, SMEM_BYTES);

    prep_weights_kernel<<<1, 256>>>(filter1);

    dim3 grid(RES / TILE_H, NBATCH);
    ca_fused_kernel<<<grid, 256, SMEM_BYTES>>>(psi, bias1, w2, b2, w3, b3, out);
}